// round 16
// baseline (speedup 1.0000x reference)
#include <cuda_runtime.h>
#include <cuda_fp16.h>
#include <cuda_bf16.h>

#define N_NODES 1200000
#define E_EDGES 12000000
#define D_IN    10
#define D_H     20
#define D_ENC   5
#define VEC     6
#define B_ROWS  200000
#define TB 256

// ---- scratch (device globals; allocation-free) ----
__device__ float  g_deg [N_NODES];
__device__ float  g_dinv[N_NODES];
// layer-1 gather source: (x+po)*dinv, fp16, 16-half rows (32B -> 1 sector)
__device__ __half g_x1  [N_NODES * 16];
// layer-1 accumulator: fp16, 16-half rows (32B; v4 RED @0, v2 RED @8)
__device__ __half g_acc1[N_NODES * 16];
// layer-2 gather source: h2*dinv, fp16, 8-half rows (16B, halfs 5-7 zero)
__device__ __half g_h2  [N_NODES * 8];
// layer-2 accumulator: fp16, 8-half rows (16B) -> one v4 RED
__device__ __half g_acc2[N_NODES * 8];

__constant__ float PO[10] = {
    0.0f, 0.8414709848f, 0.9092974268f, 0.1411200081f, -0.7568024953f,
    -0.9589242747f, -0.2794154982f, 0.6569865987f, 0.9893582466f, 0.4121184852f
};

// exact gelu via erff (identical to x*Phi(x), cheaper than normcdff)
__device__ __forceinline__ float gelu_exact(float v) {
    return 0.5f * v * (1.0f + erff(v * 0.7071067811865476f));
}

// packed f32x2 helpers (sm_103a; PTX-only)
__device__ __forceinline__ unsigned long long pack2(float a, float b) {
    unsigned long long r;
    asm("mov.b64 %0, {%1,%2};" : "=l"(r) : "f"(a), "f"(b));
    return r;
}
__device__ __forceinline__ void unpack2(unsigned long long v, float& a, float& b) {
    asm("mov.b64 {%0,%1}, %2;" : "=f"(a), "=f"(b) : "l"(v));
}
__device__ __forceinline__ unsigned long long fma2(unsigned long long a,
                                                   unsigned long long b,
                                                   unsigned long long c) {
    unsigned long long d;
    asm("fma.rn.f32x2 %0, %1, %2, %3;" : "=l"(d) : "l"(a), "l"(b), "l"(c));
    return d;
}

__device__ __forceinline__ void red_add_v4h2(__half* p, unsigned a, unsigned b,
                                             unsigned c, unsigned d) {
    asm volatile("red.global.add.noftz.v4.f16x2 [%0], {%1,%2,%3,%4};"
                 :: "l"(p), "r"(a), "r"(b), "r"(c), "r"(d) : "memory");
}
__device__ __forceinline__ void red_add_v2h2(__half* p, unsigned a, unsigned b) {
    asm volatile("red.global.add.noftz.v2.f16x2 [%0], {%1,%2};"
                 :: "l"(p), "r"(a), "r"(b) : "memory");
}

// ---------------------------------------------------------------- kernels

// degree histogram: 4 edges per thread via one int4 streaming load
__global__ void k_deg4(const int* __restrict__ ei) {
    int t = blockIdx.x * blockDim.x + threadIdx.x;
    int base = t * 4;
    if (base + 3 < E_EDGES) {
        int4 d4 = __ldcs(reinterpret_cast<const int4*>(ei + E_EDGES + base));
        atomicAdd(&g_deg[d4.x], 1.0f);
        atomicAdd(&g_deg[d4.y], 1.0f);
        atomicAdd(&g_deg[d4.z], 1.0f);
        atomicAdd(&g_deg[d4.w], 1.0f);
    } else {
        for (int e = base; e < E_EDGES; e++)
            atomicAdd(&g_deg[__ldcs(ei + E_EDGES + e)], 1.0f);
    }
}

// dinv; write fp16 (x+po)*dinv gather row (32B padded) + acc init (self term)
__global__ void k_node1(const float* __restrict__ x) {
    int i = blockIdx.x * blockDim.x + threadIdx.x;
    if (i >= N_NODES) return;

    float dinv = rsqrtf(g_deg[i] + 1.0f);
    g_dinv[i] = dinv;

    __half hv[16];
#pragma unroll
    for (int j = 0; j < D_IN; j++) {
        float v = (__ldcs(x + (size_t)i * D_IN + j) + PO[j]) * dinv;
        hv[j] = __float2half_rn(v);
    }
#pragma unroll
    for (int j = D_IN; j < 16; j++) hv[j] = __float2half_rn(0.f);

    const uint4* src4 = reinterpret_cast<const uint4*>(hv);
    __half* hp = &g_x1[(size_t)i * 16];
    reinterpret_cast<uint4*>(hp)[0] = src4[0];
    reinterpret_cast<uint4*>(hp)[1] = src4[1];

    __half* ap = &g_acc1[(size_t)i * 16];
    *reinterpret_cast<uint4*>(ap)     = src4[0];
    *reinterpret_cast<uint2*>(ap + 8) = reinterpret_cast<const uint2*>(hv)[2];
}

// layer-1 edge scatter: 4 edges/thread (int4 idx); 1-sector gather -> v4+v2 REDs
__global__ void k_edge1(const int* __restrict__ ei) {
    int t = blockIdx.x * blockDim.x + threadIdx.x;
    if (t * 4 >= E_EDGES) return;
    int4 ss = __ldcs(reinterpret_cast<const int4*>(ei) + t);
    int4 dd = __ldcs(reinterpret_cast<const int4*>(ei + E_EDGES) + t);

    const int sv[4] = {ss.x, ss.y, ss.z, ss.w};
    const int dv[4] = {dd.x, dd.y, dd.z, dd.w};
#pragma unroll
    for (int q = 0; q < 4; q++) {
        const __half* hp = &g_x1[(size_t)sv[q] * 16];
        uint4 a0 = reinterpret_cast<const uint4*>(hp)[0];
        uint2 a1 = *reinterpret_cast<const uint2*>(hp + 8);
        __half* ad = &g_acc1[(size_t)dv[q] * 16];
        red_add_v4h2(ad,     a0.x, a0.y, a0.z, a0.w);
        red_add_v2h2(ad + 8, a1.x, a1.y);
    }
}

// t = acc1 (10-dim); h1 = gelu(dinv*(t@W1) + b1); h2 = (h1@W2)*dinv; write h2+acc2
__global__ void k_node2(const float* __restrict__ W1, const float* __restrict__ b1,
                        const float* __restrict__ W2) {
    __shared__ float sW1[D_IN * D_H];   // 200, rows of 20 (even pairs 8B-aligned)
    __shared__ float sW2[D_H * D_ENC];  // 100
    __shared__ float sb[D_H];
    if (threadIdx.x < D_IN * D_H) sW1[threadIdx.x] = W1[threadIdx.x];
    if (threadIdx.x < D_H * D_ENC) sW2[threadIdx.x] = W2[threadIdx.x];
    if (threadIdx.x < D_H) sb[threadIdx.x] = b1[threadIdx.x];
    __syncthreads();

    int i = blockIdx.x * blockDim.x + threadIdx.x;
    if (i >= N_NODES) return;

    float dinv = g_dinv[i];

    const __half* ap = &g_acc1[(size_t)i * 16];
    uint4 wa = *reinterpret_cast<const uint4*>(ap);
    uint2 wb = *reinterpret_cast<const uint2*>(ap + 8);
    __half2 h2v[6];
    *reinterpret_cast<uint4*>(&h2v[0]) = wa;
    *reinterpret_cast<uint2*>(&h2v[4]) = wb;

    float t[D_IN];
#pragma unroll
    for (int k = 0; k < 5; k++) {
        float2 f = __half22float2(h2v[k]);
        t[2*k] = f.x; t[2*k+1] = f.y;
    }

    // W1 matmul with packed f32x2 FMAs: 20 outputs = 10 pairs
    unsigned long long a1[10];
#pragma unroll
    for (int p = 0; p < 10; p++) a1[p] = 0ULL;
#pragma unroll
    for (int j = 0; j < D_IN; j++) {
        unsigned long long tj = pack2(t[j], t[j]);
#pragma unroll
        for (int p = 0; p < 10; p++)
            a1[p] = fma2(tj, *reinterpret_cast<const unsigned long long*>(&sW1[j * D_H + 2*p]), a1[p]);
    }

    float h1[D_H];
#pragma unroll
    for (int p = 0; p < 10; p++) {
        float s0, s1;
        unpack2(a1[p], s0, s1);
        h1[2*p]   = gelu_exact(fmaf(dinv, s0, sb[2*p]));
        h1[2*p+1] = gelu_exact(fmaf(dinv, s1, sb[2*p+1]));
    }

    float h2[D_ENC];
#pragma unroll
    for (int c = 0; c < D_ENC; c++) {
        float s = 0.0f;
#pragma unroll
        for (int k = 0; k < D_H; k++) s = fmaf(h1[k], sW2[k * D_ENC + c], s);
        h2[c] = s * dinv;   // pre-scaled by source dinv
    }

    __half hv[8];
#pragma unroll
    for (int k = 0; k < D_ENC; k++) hv[k] = __float2half_rn(h2[k]);
#pragma unroll
    for (int k = D_ENC; k < 8; k++) hv[k] = __float2half_rn(0.f);
    uint4 pack = *reinterpret_cast<const uint4*>(hv);
    *reinterpret_cast<uint4*>(&g_h2  [(size_t)i * 8]) = pack;
    *reinterpret_cast<uint4*>(&g_acc2[(size_t)i * 8]) = pack;
}

// layer-2 edge scatter: 4 edges/thread (int4 idx); gather -> single v4 RED
__global__ void k_edge2(const int* __restrict__ ei) {
    int t = blockIdx.x * blockDim.x + threadIdx.x;
    if (t * 4 >= E_EDGES) return;
    int4 ss = __ldcs(reinterpret_cast<const int4*>(ei) + t);
    int4 dd = __ldcs(reinterpret_cast<const int4*>(ei + E_EDGES) + t);

    const int sv[4] = {ss.x, ss.y, ss.z, ss.w};
    const int dv[4] = {dd.x, dd.y, dd.z, dd.w};
#pragma unroll
    for (int q = 0; q < 4; q++) {
        uint4 w = *reinterpret_cast<const uint4*>(&g_h2[(size_t)sv[q] * 8]);
        red_add_v4h2(&g_acc2[(size_t)dv[q] * 8], w.x, w.y, w.z, w.w);
    }
}

// epilogue with packed f32x2 matmuls
__global__ void k_final(const float* __restrict__ b2,
                        const float* __restrict__ We, const float* __restrict__ be,
                        const float* __restrict__ Wd, const float* __restrict__ bd,
                        const float* __restrict__ Wr, const float* __restrict__ br,
                        float* __restrict__ out) {
    __shared__ float sWe[30 * 30];
    __shared__ float sWd[30 * 60];
    __shared__ float sWr[30 * 7];
    __shared__ float sbe[30], sbd[60], sbr[7], sb2[5];

    for (int t = threadIdx.x; t < 900;  t += blockDim.x) sWe[t] = We[t];
    for (int t = threadIdx.x; t < 1800; t += blockDim.x) sWd[t] = Wd[t];
    for (int t = threadIdx.x; t < 210;  t += blockDim.x) sWr[t] = Wr[t];
    if (threadIdx.x < 30) sbe[threadIdx.x] = be[threadIdx.x];
    if (threadIdx.x < 60) sbd[threadIdx.x] = bd[threadIdx.x];
    if (threadIdx.x < 7)  sbr[threadIdx.x] = br[threadIdx.x];
    if (threadIdx.x < 5)  sb2[threadIdx.x] = b2[threadIdx.x];
    __syncthreads();

    int b = blockIdx.x * blockDim.x + threadIdx.x;
    if (b >= B_ROWS) return;

    float r[30];
#pragma unroll
    for (int v = 0; v < VEC; v++) {
        int node = b * VEC + v;
        float dinv = g_dinv[node];
        uint4 w = *reinterpret_cast<const uint4*>(&g_acc2[(size_t)node * 8]);
        const __half* hv = reinterpret_cast<const __half*>(&w);
#pragma unroll
        for (int k = 0; k < D_ENC; k++)
            r[v * D_ENC + k] = gelu_exact(fmaf(dinv, __half2float(hv[k]), sb2[k]));
    }

    // enc = r@We + be : 30 outputs = 15 pairs
    unsigned long long accE[15];
#pragma unroll
    for (int p = 0; p < 15; p++)
        accE[p] = *reinterpret_cast<const unsigned long long*>(&sbe[2*p]);
#pragma unroll
    for (int j = 0; j < 30; j++) {
        unsigned long long rj = pack2(r[j], r[j]);
#pragma unroll
        for (int p = 0; p < 15; p++)
            accE[p] = fma2(rj, *reinterpret_cast<const unsigned long long*>(&sWe[j * 30 + 2*p]), accE[p]);
    }
    float enc[30];
#pragma unroll
    for (int p = 0; p < 15; p++) unpack2(accE[p], enc[2*p], enc[2*p+1]);

    // x1 = enc@Wr + br (7 outputs, scalar)
    float* px1 = out + (size_t)b * 7;
#pragma unroll
    for (int o = 0; o < 7; o++) {
        float s = sbr[o];
#pragma unroll
        for (int j = 0; j < 30; j++) s = fmaf(enc[j], sWr[j * 7 + o], s);
        px1[o] = s;
    }

    // enc region (8B-aligned rows) -> paired stores
    float* pe = out + (size_t)B_ROWS * 7 + (size_t)b * 30;
#pragma unroll
    for (int p = 0; p < 15; p++)
        *reinterpret_cast<unsigned long long*>(&pe[2*p]) = accE[p];

    // out = gelu(enc)@Wd + bd : 60 outputs = 2 halves of 15 pairs
    float rg[30];
#pragma unroll
    for (int j = 0; j < 30; j++) rg[j] = gelu_exact(enc[j]);

    float* po = out + (size_t)B_ROWS * 37 + (size_t)b * 60;
#pragma unroll
    for (int half = 0; half < 2; half++) {
        unsigned long long accD[15];
#pragma unroll
        for (int p = 0; p < 15; p++)
            accD[p] = *reinterpret_cast<const unsigned long long*>(&sbd[half * 30 + 2*p]);
#pragma unroll
        for (int j = 0; j < 30; j++) {
            unsigned long long rj = pack2(rg[j], rg[j]);
#pragma unroll
            for (int p = 0; p < 15; p++)
                accD[p] = fma2(rj, *reinterpret_cast<const unsigned long long*>(&sWd[j * 60 + half * 30 + 2*p]), accD[p]);
        }
#pragma unroll
        for (int p = 0; p < 15; p++)
            *reinterpret_cast<unsigned long long*>(&po[half * 30 + 2*p]) = accD[p];
    }
}

// ---------------------------------------------------------------- launch

extern "C" void kernel_launch(void* const* d_in, const int* in_sizes, int n_in,
                              void* d_out, int out_size) {
    const float* x  = (const float*)d_in[0];
    const int*   ei = (const int*)  d_in[1];
    const float* W1 = (const float*)d_in[2];
    const float* b1 = (const float*)d_in[3];
    const float* W2 = (const float*)d_in[4];
    const float* b2 = (const float*)d_in[5];
    const float* We = (const float*)d_in[6];
    const float* be = (const float*)d_in[7];
    const float* Wd = (const float*)d_in[8];
    const float* bd = (const float*)d_in[9];
    const float* Wr = (const float*)d_in[10];
    const float* br = (const float*)d_in[11];
    float* out = (float*)d_out;

    static float* deg_ptr = nullptr;
    if (!deg_ptr) cudaGetSymbolAddress((void**)&deg_ptr, g_deg);

    int gN  = (N_NODES + TB - 1) / TB;
    int gE4 = (E_EDGES / 4 + TB - 1) / TB;
    int gB  = (B_ROWS + TB - 1) / TB;

    cudaMemsetAsync(deg_ptr, 0, N_NODES * sizeof(float));
    k_deg4<<<gE4, TB>>>(ei);
    k_node1<<<gN, TB>>>(x);
    k_edge1<<<gE4, TB>>>(ei);
    k_node2<<<gN, TB>>>(W1, b1, W2);
    k_edge2<<<gE4, TB>>>(ei);
    k_final<<<gB, TB>>>(b2, We, be, Wd, bd, Wr, br, out);
}

// round 17
// speedup vs baseline: 1.0148x; 1.0148x over previous
#include <cuda_runtime.h>
#include <cuda_fp16.h>
#include <cuda_bf16.h>

#define N_NODES 1200000
#define E_EDGES 12000000
#define D_IN    10
#define D_H     20
#define D_ENC   5
#define VEC     6
#define B_ROWS  200000
#define TB 256

// ---- scratch (device globals; allocation-free) ----
__device__ float  g_deg [N_NODES];
__device__ float  g_dinv[N_NODES];
// layer-1 gather source: (x+po)*dinv, fp16, 16-half rows (32B -> 1 sector)
__device__ __half g_x1  [N_NODES * 16];
// layer-1 accumulator: fp16, 16-half rows (32B; v4 RED @0, v2 RED @8)
__device__ __half g_acc1[N_NODES * 16];
// layer-2 gather source: h2*dinv, fp16, 8-half rows (16B, halfs 5-7 zero)
__device__ __half g_h2  [N_NODES * 8];
// layer-2 accumulator: fp16, 8-half rows (16B) -> one v4 RED
__device__ __half g_acc2[N_NODES * 8];

__constant__ float PO[10] = {
    0.0f, 0.8414709848f, 0.9092974268f, 0.1411200081f, -0.7568024953f,
    -0.9589242747f, -0.2794154982f, 0.6569865987f, 0.9893582466f, 0.4121184852f
};

// exact gelu via erff (identical to x*Phi(x), cheaper than normcdff)
__device__ __forceinline__ float gelu_exact(float v) {
    return 0.5f * v * (1.0f + erff(v * 0.7071067811865476f));
}

// packed f32x2 helpers (sm_103a; PTX-only)
__device__ __forceinline__ unsigned long long pack2(float a, float b) {
    unsigned long long r;
    asm("mov.b64 %0, {%1,%2};" : "=l"(r) : "f"(a), "f"(b));
    return r;
}
__device__ __forceinline__ void unpack2(unsigned long long v, float& a, float& b) {
    asm("mov.b64 {%0,%1}, %2;" : "=f"(a), "=f"(b) : "l"(v));
}
__device__ __forceinline__ unsigned long long fma2(unsigned long long a,
                                                   unsigned long long b,
                                                   unsigned long long c) {
    unsigned long long d;
    asm("fma.rn.f32x2 %0, %1, %2, %3;" : "=l"(d) : "l"(a), "l"(b), "l"(c));
    return d;
}

__device__ __forceinline__ void red_add_v4h2(__half* p, unsigned a, unsigned b,
                                             unsigned c, unsigned d) {
    asm volatile("red.global.add.noftz.v4.f16x2 [%0], {%1,%2,%3,%4};"
                 :: "l"(p), "r"(a), "r"(b), "r"(c), "r"(d) : "memory");
}
__device__ __forceinline__ void red_add_v2h2(__half* p, unsigned a, unsigned b) {
    asm volatile("red.global.add.noftz.v2.f16x2 [%0], {%1,%2};"
                 :: "l"(p), "r"(a), "r"(b) : "memory");
}

// ---------------------------------------------------------------- kernels

// degree histogram: 4 edges per thread via one int4 streaming load
__global__ void k_deg4(const int* __restrict__ ei) {
    int t = blockIdx.x * blockDim.x + threadIdx.x;
    int base = t * 4;
    if (base + 3 < E_EDGES) {
        int4 d4 = __ldcs(reinterpret_cast<const int4*>(ei + E_EDGES + base));
        atomicAdd(&g_deg[d4.x], 1.0f);
        atomicAdd(&g_deg[d4.y], 1.0f);
        atomicAdd(&g_deg[d4.z], 1.0f);
        atomicAdd(&g_deg[d4.w], 1.0f);
    } else {
        for (int e = base; e < E_EDGES; e++)
            atomicAdd(&g_deg[__ldcs(ei + E_EDGES + e)], 1.0f);
    }
    cudaTriggerProgrammaticLaunchCompletion();
}

// dinv; write fp16 (x+po)*dinv gather row (32B padded) + acc init (self term)
// PDL prologue: stream own x row before waiting on the deg pass.
__global__ void k_node1(const float* __restrict__ x) {
    int i = blockIdx.x * blockDim.x + threadIdx.x;

    float xr[D_IN];
    if (i < N_NODES) {
        const float2* xp = reinterpret_cast<const float2*>(x + (size_t)i * D_IN);
#pragma unroll
        for (int q = 0; q < 5; q++) {
            float2 v = __ldcs(xp + q);
            xr[2*q] = v.x; xr[2*q+1] = v.y;
        }
    }

    cudaGridDependencySynchronize();
    if (i >= N_NODES) return;

    float dinv = rsqrtf(g_deg[i] + 1.0f);
    g_dinv[i] = dinv;

    __half hv[16];
#pragma unroll
    for (int j = 0; j < D_IN; j++)
        hv[j] = __float2half_rn((xr[j] + PO[j]) * dinv);
#pragma unroll
    for (int j = D_IN; j < 16; j++) hv[j] = __float2half_rn(0.f);

    const uint4* src4 = reinterpret_cast<const uint4*>(hv);
    __half* hp = &g_x1[(size_t)i * 16];
    reinterpret_cast<uint4*>(hp)[0] = src4[0];
    reinterpret_cast<uint4*>(hp)[1] = src4[1];

    __half* ap = &g_acc1[(size_t)i * 16];
    *reinterpret_cast<uint4*>(ap)     = src4[0];
    *reinterpret_cast<uint2*>(ap + 8) = reinterpret_cast<const uint2*>(hv)[2];

    cudaTriggerProgrammaticLaunchCompletion();
}

// layer-1 edge scatter: 4 edges/thread (int4 idx); 1-sector gather -> v4+v2 REDs
// PDL prologue: load index vectors before waiting on node1.
__global__ void k_edge1(const int* __restrict__ ei) {
    int t = blockIdx.x * blockDim.x + threadIdx.x;
    bool act = (t * 4 < E_EDGES);
    int4 ss, dd;
    if (act) {
        ss = __ldcs(reinterpret_cast<const int4*>(ei) + t);
        dd = __ldcs(reinterpret_cast<const int4*>(ei + E_EDGES) + t);
    }

    cudaGridDependencySynchronize();
    if (!act) return;

    const int sv[4] = {ss.x, ss.y, ss.z, ss.w};
    const int dv[4] = {dd.x, dd.y, dd.z, dd.w};
#pragma unroll
    for (int q = 0; q < 4; q++) {
        const __half* hp = &g_x1[(size_t)sv[q] * 16];
        uint4 a0 = reinterpret_cast<const uint4*>(hp)[0];
        uint2 a1 = *reinterpret_cast<const uint2*>(hp + 8);
        __half* ad = &g_acc1[(size_t)dv[q] * 16];
        red_add_v4h2(ad,     a0.x, a0.y, a0.z, a0.w);
        red_add_v2h2(ad + 8, a1.x, a1.y);
    }
    cudaTriggerProgrammaticLaunchCompletion();
}

// t = acc1 (10-dim); h1 = gelu(dinv*(t@W1) + b1); h2 = (h1@W2)*dinv; write h2+acc2
// PDL prologue: stage weights in smem before waiting on edge1.
__global__ void k_node2(const float* __restrict__ W1, const float* __restrict__ b1,
                        const float* __restrict__ W2) {
    __shared__ float sW1[D_IN * D_H];   // 200
    __shared__ float sW2[D_H * D_ENC];  // 100
    __shared__ float sb[D_H];
    if (threadIdx.x < D_IN * D_H) sW1[threadIdx.x] = W1[threadIdx.x];
    if (threadIdx.x < D_H * D_ENC) sW2[threadIdx.x] = W2[threadIdx.x];
    if (threadIdx.x < D_H) sb[threadIdx.x] = b1[threadIdx.x];
    __syncthreads();

    cudaGridDependencySynchronize();

    int i = blockIdx.x * blockDim.x + threadIdx.x;
    if (i >= N_NODES) return;

    float dinv = g_dinv[i];

    const __half* ap = &g_acc1[(size_t)i * 16];
    uint4 wa = *reinterpret_cast<const uint4*>(ap);
    uint2 wb = *reinterpret_cast<const uint2*>(ap + 8);
    __half2 h2v[6];
    *reinterpret_cast<uint4*>(&h2v[0]) = wa;
    *reinterpret_cast<uint2*>(&h2v[4]) = wb;

    float t[D_IN];
#pragma unroll
    for (int k = 0; k < 5; k++) {
        float2 f = __half22float2(h2v[k]);
        t[2*k] = f.x; t[2*k+1] = f.y;
    }

    // W1 matmul with packed f32x2 FMAs: 20 outputs = 10 pairs
    unsigned long long a1[10];
#pragma unroll
    for (int p = 0; p < 10; p++) a1[p] = 0ULL;
#pragma unroll
    for (int j = 0; j < D_IN; j++) {
        unsigned long long tj = pack2(t[j], t[j]);
#pragma unroll
        for (int p = 0; p < 10; p++)
            a1[p] = fma2(tj, *reinterpret_cast<const unsigned long long*>(&sW1[j * D_H + 2*p]), a1[p]);
    }

    float h1[D_H];
#pragma unroll
    for (int p = 0; p < 10; p++) {
        float s0, s1;
        unpack2(a1[p], s0, s1);
        h1[2*p]   = gelu_exact(fmaf(dinv, s0, sb[2*p]));
        h1[2*p+1] = gelu_exact(fmaf(dinv, s1, sb[2*p+1]));
    }

    float h2[D_ENC];
#pragma unroll
    for (int c = 0; c < D_ENC; c++) {
        float s = 0.0f;
#pragma unroll
        for (int k = 0; k < D_H; k++) s = fmaf(h1[k], sW2[k * D_ENC + c], s);
        h2[c] = s * dinv;   // pre-scaled by source dinv
    }

    __half hv[8];
#pragma unroll
    for (int k = 0; k < D_ENC; k++) hv[k] = __float2half_rn(h2[k]);
#pragma unroll
    for (int k = D_ENC; k < 8; k++) hv[k] = __float2half_rn(0.f);
    uint4 pack = *reinterpret_cast<const uint4*>(hv);
    *reinterpret_cast<uint4*>(&g_h2  [(size_t)i * 8]) = pack;
    *reinterpret_cast<uint4*>(&g_acc2[(size_t)i * 8]) = pack;

    cudaTriggerProgrammaticLaunchCompletion();
}

// layer-2 edge scatter: 4 edges/thread (int4 idx); gather -> single v4 RED
__global__ void k_edge2(const int* __restrict__ ei) {
    int t = blockIdx.x * blockDim.x + threadIdx.x;
    bool act = (t * 4 < E_EDGES);
    int4 ss, dd;
    if (act) {
        ss = __ldcs(reinterpret_cast<const int4*>(ei) + t);
        dd = __ldcs(reinterpret_cast<const int4*>(ei + E_EDGES) + t);
    }

    cudaGridDependencySynchronize();
    if (!act) return;

    const int sv[4] = {ss.x, ss.y, ss.z, ss.w};
    const int dv[4] = {dd.x, dd.y, dd.z, dd.w};
#pragma unroll
    for (int q = 0; q < 4; q++) {
        uint4 w = *reinterpret_cast<const uint4*>(&g_h2[(size_t)sv[q] * 8]);
        red_add_v4h2(&g_acc2[(size_t)dv[q] * 8], w.x, w.y, w.z, w.w);
    }
    cudaTriggerProgrammaticLaunchCompletion();
}

// epilogue with packed f32x2 matmuls; PDL prologue = smem weight staging
__global__ void k_final(const float* __restrict__ b2,
                        const float* __restrict__ We, const float* __restrict__ be,
                        const float* __restrict__ Wd, const float* __restrict__ bd,
                        const float* __restrict__ Wr, const float* __restrict__ br,
                        float* __restrict__ out) {
    __shared__ float sWe[30 * 30];
    __shared__ float sWd[30 * 60];
    __shared__ float sWr[30 * 7];
    __shared__ float sbe[30], sbd[60], sbr[7], sb2[5];

    for (int t = threadIdx.x; t < 900;  t += blockDim.x) sWe[t] = We[t];
    for (int t = threadIdx.x; t < 1800; t += blockDim.x) sWd[t] = Wd[t];
    for (int t = threadIdx.x; t < 210;  t += blockDim.x) sWr[t] = Wr[t];
    if (threadIdx.x < 30) sbe[threadIdx.x] = be[threadIdx.x];
    if (threadIdx.x < 60) sbd[threadIdx.x] = bd[threadIdx.x];
    if (threadIdx.x < 7)  sbr[threadIdx.x] = br[threadIdx.x];
    if (threadIdx.x < 5)  sb2[threadIdx.x] = b2[threadIdx.x];
    __syncthreads();

    cudaGridDependencySynchronize();

    int b = blockIdx.x * blockDim.x + threadIdx.x;
    if (b >= B_ROWS) return;

    float r[30];
#pragma unroll
    for (int v = 0; v < VEC; v++) {
        int node = b * VEC + v;
        float dinv = g_dinv[node];
        uint4 w = *reinterpret_cast<const uint4*>(&g_acc2[(size_t)node * 8]);
        const __half* hv = reinterpret_cast<const __half*>(&w);
#pragma unroll
        for (int k = 0; k < D_ENC; k++)
            r[v * D_ENC + k] = gelu_exact(fmaf(dinv, __half2float(hv[k]), sb2[k]));
    }

    // enc = r@We + be : 30 outputs = 15 pairs
    unsigned long long accE[15];
#pragma unroll
    for (int p = 0; p < 15; p++)
        accE[p] = *reinterpret_cast<const unsigned long long*>(&sbe[2*p]);
#pragma unroll
    for (int j = 0; j < 30; j++) {
        unsigned long long rj = pack2(r[j], r[j]);
#pragma unroll
        for (int p = 0; p < 15; p++)
            accE[p] = fma2(rj, *reinterpret_cast<const unsigned long long*>(&sWe[j * 30 + 2*p]), accE[p]);
    }
    float enc[30];
#pragma unroll
    for (int p = 0; p < 15; p++) unpack2(accE[p], enc[2*p], enc[2*p+1]);

    // x1 = enc@Wr + br (7 outputs, scalar)
    float* px1 = out + (size_t)b * 7;
#pragma unroll
    for (int o = 0; o < 7; o++) {
        float s = sbr[o];
#pragma unroll
        for (int j = 0; j < 30; j++) s = fmaf(enc[j], sWr[j * 7 + o], s);
        px1[o] = s;
    }

    // enc region (8B-aligned rows) -> paired stores
    float* pe = out + (size_t)B_ROWS * 7 + (size_t)b * 30;
#pragma unroll
    for (int p = 0; p < 15; p++)
        *reinterpret_cast<unsigned long long*>(&pe[2*p]) = accE[p];

    // out = gelu(enc)@Wd + bd : 60 outputs = 2 halves of 15 pairs
    float rg[30];
#pragma unroll
    for (int j = 0; j < 30; j++) rg[j] = gelu_exact(enc[j]);

    float* po = out + (size_t)B_ROWS * 37 + (size_t)b * 60;
#pragma unroll
    for (int half = 0; half < 2; half++) {
        unsigned long long accD[15];
#pragma unroll
        for (int p = 0; p < 15; p++)
            accD[p] = *reinterpret_cast<const unsigned long long*>(&sbd[half * 30 + 2*p]);
#pragma unroll
        for (int j = 0; j < 30; j++) {
            unsigned long long rj = pack2(rg[j], rg[j]);
#pragma unroll
            for (int p = 0; p < 15; p++)
                accD[p] = fma2(rj, *reinterpret_cast<const unsigned long long*>(&sWd[j * 60 + half * 30 + 2*p]), accD[p]);
        }
#pragma unroll
        for (int p = 0; p < 15; p++)
            *reinterpret_cast<unsigned long long*>(&po[half * 30 + 2*p]) = accD[p];
    }
}

// ---------------------------------------------------------------- launch

template <typename K, typename... Args>
static void launch_pdl(K kernel, int grid, int block, Args... args) {
    cudaLaunchConfig_t cfg = {};
    cfg.gridDim = dim3(grid, 1, 1);
    cfg.blockDim = dim3(block, 1, 1);
    cudaLaunchAttribute attr[1];
    attr[0].id = cudaLaunchAttributeProgrammaticStreamSerialization;
    attr[0].val.programmaticStreamSerializationAllowed = 1;
    cfg.attrs = attr;
    cfg.numAttrs = 1;
    cudaLaunchKernelEx(&cfg, kernel, args...);
}

extern "C" void kernel_launch(void* const* d_in, const int* in_sizes, int n_in,
                              void* d_out, int out_size) {
    const float* x  = (const float*)d_in[0];
    const int*   ei = (const int*)  d_in[1];
    const float* W1 = (const float*)d_in[2];
    const float* b1 = (const float*)d_in[3];
    const float* W2 = (const float*)d_in[4];
    const float* b2 = (const float*)d_in[5];
    const float* We = (const float*)d_in[6];
    const float* be = (const float*)d_in[7];
    const float* Wd = (const float*)d_in[8];
    const float* bd = (const float*)d_in[9];
    const float* Wr = (const float*)d_in[10];
    const float* br = (const float*)d_in[11];
    float* out = (float*)d_out;

    static float* deg_ptr = nullptr;
    if (!deg_ptr) cudaGetSymbolAddress((void**)&deg_ptr, g_deg);

    int gN  = (N_NODES + TB - 1) / TB;
    int gE4 = (E_EDGES / 4 + TB - 1) / TB;
    int gB  = (B_ROWS + TB - 1) / TB;

    cudaMemsetAsync(deg_ptr, 0, N_NODES * sizeof(float));
    k_deg4<<<gE4, TB>>>(ei);                       // normal launch (follows memset)
    launch_pdl(k_node1, gN,  TB, x);
    launch_pdl(k_edge1, gE4, TB, ei);
    launch_pdl(k_node2, gN,  TB, W1, b1, W2);
    launch_pdl(k_edge2, gE4, TB, ei);
    launch_pdl(k_final, gB,  TB, b2, We, be, Wd, bd, Wr, br, out);
}